// round 7
// baseline (speedup 1.0000x reference)
#include <cuda_runtime.h>
#include <cuda_bf16.h>
#include <cstdint>
#include <math.h>

#define NBATCH 64
#define NT     512
#define NROWS  (NBATCH * NT)
#define NB     128

// ---------------- device scratch ----------------
__device__ float g_pre1[NROWS * 1024];
__device__ float g_pre2[NROWS * 512];
__device__ float g_memT[2][256 * 64];          // [m][b] double-buffered
__device__ float g_Bp[NB * 128 * 64];          // [i][o][b] v2-head partials
__device__ float g_bias1[1024];
__device__ float g_bias2[512];
__device__ unsigned g_barCnt;
// bf16 split operands (K-concat trick)
__device__ __nv_bfloat16 g_X3[NROWS * 1536];   // [Ah|Ah|Al]
__device__ __nv_bfloat16 g_W013[1024 * 1536];  // [Wh|Wl|Wh]
__device__ __nv_bfloat16 g_W023[512 * 1536];
__device__ __nv_bfloat16 g_Wt3[384 * 3840];    // tail weights [Wh|Wl|Wh], K=1280
__device__ __nv_bfloat16 g_At3[NROWS * 3840];  // tail A [Ah|Ah|Al], K=1280 (filled by loop)

// ---------------- prep ----------------
__global__ void prep_kernel(const float* __restrict__ b01, const float* __restrict__ bm1,
                            const float* __restrict__ b02, const float* __restrict__ b12,
                            const float* __restrict__ bm2, const float* __restrict__ memory) {
    int i = blockIdx.x * blockDim.x + threadIdx.x;
    int n = gridDim.x * blockDim.x;
    if (i == 0) g_barCnt = 0u;
    for (int j = i; j < 1024; j += n) g_bias1[j] = b01[j] + bm1[j];
    for (int j = i; j < 512; j += n) g_bias2[j] = b02[j] + b12[j] + bm2[j];
    for (int j = i; j < 256 * 64; j += n) {
        int m = j & 255, b = j >> 8;
        float x = memory[j];                    // memory[b][m], j = b*256+m
        g_memT[0][m * 64 + b] = x;
        __nv_bfloat16 h = __float2bfloat16(x);
        __nv_bfloat16 l = __float2bfloat16(x - __bfloat162float(h));
        size_t base = (size_t)(b * NT) * 3840;  // row t=0
        g_At3[base + 1024 + m] = h;
        g_At3[base + 2304 + m] = h;
        g_At3[base + 3584 + m] = l;
    }
}

// split fp32 -> bf16 hi/lo, K-concat. aMode: [h|h|l]  else (W): [h|l|h]
__global__ void split3_kernel(const float* __restrict__ src, __nv_bfloat16* __restrict__ dst,
                              int K, int total, int aMode) {
    for (int i = blockIdx.x * blockDim.x + threadIdx.x; i < total; i += gridDim.x * blockDim.x) {
        int r = i / K, k = i % K;
        float x = src[i];
        __nv_bfloat16 h = __float2bfloat16(x);
        __nv_bfloat16 l = __float2bfloat16(x - __bfloat162float(h));
        __nv_bfloat16* d = dst + (size_t)r * 3 * K + k;
        d[0] = h;
        d[K] = aMode ? h : l;
        d[2 * K] = aMode ? l : h;
    }
}

// tail W: rows o=0..383 map to W12[o+128], Wm2[o+128]; layout [Wh|Wl|Wh] over K=1280
__global__ void splitWtail_kernel(const float* __restrict__ W12, const float* __restrict__ Wm2) {
    for (int i = blockIdx.x * blockDim.x + threadIdx.x; i < 384 * 1280; i += gridDim.x * blockDim.x) {
        int o = i / 1280, k = i % 1280;
        float x = (k < 1024) ? W12[(o + 128) * 1024 + k] : Wm2[(o + 128) * 256 + (k - 1024)];
        __nv_bfloat16 h = __float2bfloat16(x);
        __nv_bfloat16 l = __float2bfloat16(x - __bfloat162float(h));
        __nv_bfloat16* d = g_Wt3 + (size_t)o * 3840 + k;
        d[0] = h; d[1280] = l; d[2560] = h;
    }
}

// ---------------- bf16 tensor-core GEMM (passing; + swapxy for L2 reuse) ----------------
__global__ void __launch_bounds__(256) hgemm_kernel(const __nv_bfloat16* __restrict__ A,
                                                    const __nv_bfloat16* __restrict__ W, int K,
                                                    float* __restrict__ C, int ldc,
                                                    const float* __restrict__ bias,
                                                    const float* __restrict__ addm, int addld,
                                                    int swapxy) {
    __shared__ __nv_bfloat16 sA[2][128][40];
    __shared__ __nv_bfloat16 sW[2][128][40];
    const int tid = threadIdx.x;
    const int bx = swapxy ? blockIdx.y : blockIdx.x;
    const int by = swapxy ? blockIdx.x : blockIdx.y;
    const int m0 = bx * 128, n0 = by * 128;
    const int warp = tid >> 5, lane = tid & 31;
    const int wm = (warp >> 1) * 32, wn = (warp & 1) * 64;
    const int lr = tid >> 1, lc = (tid & 1) * 16;
    float acc[2][8][4] = {};
    const __nv_bfloat16* Ag = A + (size_t)(m0 + lr) * K + lc;
    const __nv_bfloat16* Wg = W + (size_t)(n0 + lr) * K + lc;
    uint4 ra0 = *(const uint4*)Ag, ra1 = *(const uint4*)(Ag + 8);
    uint4 rw0 = *(const uint4*)Wg, rw1 = *(const uint4*)(Wg + 8);
    *(uint4*)&sA[0][lr][lc] = ra0; *(uint4*)&sA[0][lr][lc + 8] = ra1;
    *(uint4*)&sW[0][lr][lc] = rw0; *(uint4*)&sW[0][lr][lc + 8] = rw1;
    __syncthreads();
    const int nsteps = K / 32;
    for (int s = 0; s < nsteps; s++) {
        const int cur = s & 1;
        if (s + 1 < nsteps) {
            const __nv_bfloat16* An = Ag + (size_t)(s + 1) * 32;
            const __nv_bfloat16* Wn = Wg + (size_t)(s + 1) * 32;
            ra0 = *(const uint4*)An; ra1 = *(const uint4*)(An + 8);
            rw0 = *(const uint4*)Wn; rw1 = *(const uint4*)(Wn + 8);
        }
#pragma unroll
        for (int kf = 0; kf < 2; kf++) {
            const int acol = kf * 16 + (lane & 3) * 2;
            const int arow = wm + (lane >> 2);
            uint32_t af[2][4], bfr[8][2];
#pragma unroll
            for (int mi = 0; mi < 2; mi++) {
                af[mi][0] = *(uint32_t*)&sA[cur][arow + mi * 16][acol];
                af[mi][1] = *(uint32_t*)&sA[cur][arow + mi * 16 + 8][acol];
                af[mi][2] = *(uint32_t*)&sA[cur][arow + mi * 16][acol + 8];
                af[mi][3] = *(uint32_t*)&sA[cur][arow + mi * 16 + 8][acol + 8];
            }
#pragma unroll
            for (int ni = 0; ni < 8; ni++) {
                bfr[ni][0] = *(uint32_t*)&sW[cur][wn + ni * 8 + (lane >> 2)][acol];
                bfr[ni][1] = *(uint32_t*)&sW[cur][wn + ni * 8 + (lane >> 2)][acol + 8];
            }
#pragma unroll
            for (int mi = 0; mi < 2; mi++)
#pragma unroll
                for (int ni = 0; ni < 8; ni++)
                    asm volatile(
                        "mma.sync.aligned.m16n8k16.row.col.f32.bf16.bf16.f32 "
                        "{%0,%1,%2,%3}, {%4,%5,%6,%7}, {%8,%9}, {%0,%1,%2,%3};"
                        : "+f"(acc[mi][ni][0]), "+f"(acc[mi][ni][1]),
                          "+f"(acc[mi][ni][2]), "+f"(acc[mi][ni][3])
                        : "r"(af[mi][0]), "r"(af[mi][1]), "r"(af[mi][2]), "r"(af[mi][3]),
                          "r"(bfr[ni][0]), "r"(bfr[ni][1]));
        }
        __syncthreads();
        if (s + 1 < nsteps) {
            *(uint4*)&sA[cur ^ 1][lr][lc] = ra0; *(uint4*)&sA[cur ^ 1][lr][lc + 8] = ra1;
            *(uint4*)&sW[cur ^ 1][lr][lc] = rw0; *(uint4*)&sW[cur ^ 1][lr][lc + 8] = rw1;
        }
        __syncthreads();
    }
    const int r0 = lane >> 2, c0 = (lane & 3) * 2;
#pragma unroll
    for (int mi = 0; mi < 2; mi++)
#pragma unroll
        for (int ni = 0; ni < 8; ni++) {
            int gr = m0 + wm + mi * 16 + r0;
            int gc = wn + ni * 8 + c0;
            float v0 = acc[mi][ni][0], v1 = acc[mi][ni][1];
            float v2 = acc[mi][ni][2], v3 = acc[mi][ni][3];
            int gcg = n0 + gc;
            if (bias) {
                float2 bb = *(const float2*)&bias[gcg];
                v0 += bb.x; v1 += bb.y; v2 += bb.x; v3 += bb.y;
            }
            if (addm) {
                float2 a0 = *(const float2*)&addm[(size_t)gr * addld + gcg];
                float2 a1 = *(const float2*)&addm[(size_t)(gr + 8) * addld + gcg];
                v0 += a0.x; v1 += a0.y; v2 += a1.x; v3 += a1.y;
            }
            *(float2*)&C[(size_t)gr * ldc + gcg] = make_float2(v0, v1);
            *(float2*)&C[(size_t)(gr + 8) * ldc + gcg] = make_float2(v2, v3);
        }
}

// ---------------- persistent recurrent loop: 2 barriers/step ----------------
__device__ __forceinline__ void gbar(unsigned target) {
    __syncthreads();
    if (threadIdx.x == 0) {
        __threadfence();
        atomicAdd(&g_barCnt, 1u);
        while (*(volatile unsigned*)&g_barCnt < target) { }
    }
    __syncthreads();
}

// dynamic smem layout (floats):
//   sMem[16384] | v1s[512] | sW1[2048] | sW12[1024] | sW2m[256] | sRed[256]
#define SM_MEM  0
#define SM_V1S  16384
#define SM_W1   16896
#define SM_W12  18944
#define SM_W2M  19968
#define SM_RED  20224
#define SM_TOT  20480

__global__ void __launch_bounds__(256, 1) loop_kernel(const float* __restrict__ Wm1,
                                                      const float* __restrict__ W12,
                                                      const float* __restrict__ Wm2,
                                                      float* __restrict__ out) {
    extern __shared__ float sm[];
    float* sMem = sm + SM_MEM;
    float* v1s  = sm + SM_V1S;
    float* sW1  = sm + SM_W1;
    float* sW12 = sm + SM_W12;
    float* sW2m = sm + SM_W2M;
    float* sRed = sm + SM_RED;

    const int tid = threadIdx.x, blk = blockIdx.x;
    const int H0 = blk * 8;          // owned v1 rows [H0, H0+8)
    const int M0 = blk * 2;          // owned mem rows for v2 partial
    // stage-1 mapping: 4 h-pairs x 64 batch
    const int hp = tid >> 6, b1 = tid & 63;
    const int h0 = H0 + hp * 2;
    // stage-2 mapping: 32 o-groups(4) x 8 b-groups(8)
    const int og = tid >> 3, bg = tid & 7;
    const int o0 = og * 4, b0 = bg * 8;
    // stage-3 mapping
    const int iq = tid >> 6, b3 = tid & 63;

    // one-time weight staging
    for (int i = tid; i < 2048; i += 256) {      // sW1[m][hl]
        int m = i >> 3, hl = i & 7;
        sW1[i] = Wm1[(H0 + hl) * 256 + m];
    }
    for (int i = tid; i < 1024; i += 256) {      // sW12[k][o]
        int k = i >> 7, o = i & 127;
        sW12[i] = W12[o * 1024 + H0 + k];
    }
    for (int i = tid; i < 256; i += 256) {       // sW2m[ml][o]
        int ml = i >> 7, o = i & 127;
        sW2m[i] = Wm2[o * 256 + M0 + ml];
    }
    __syncthreads();

    unsigned tgt = NB;
    for (int t = 0; t < NT; t++) {
        const int par = t & 1, nxt = par ^ 1;
        // prefetch per-step globals
        const int row1 = b1 * NT + t;
        float2 p1 = *(const float2*)&g_pre1[(size_t)row1 * 1024 + h0];
        float p2v = 0.f;
        if (tid < 64) p2v = g_pre2[(size_t)(tid * NT + t) * 512 + blk];
        // stage mem slice into smem
        for (int i = tid * 4; i < 16384; i += 1024)
            *(float4*)&sMem[i] = __ldcg((const float4*)&g_memT[par][i]);
        __syncthreads();

        // ===== stage 1: v1 rows [H0,H0+8) over full K=256 =====
        float a0 = 0.f, a1 = 0.f;
#pragma unroll 8
        for (int m = 0; m < 256; m++) {
            float x = sMem[m * 64 + b1];
            float2 w = *(float2*)&sW1[m * 8 + hp * 2];
            a0 += w.x * x; a1 += w.y * x;
        }
        float v0 = p1.x + a0, v1v = p1.y + a1;
        if (H0 < 512) { v0 = tanhf(v0); v1v = tanhf(v1v); }
        else          { v0 = fmaxf(v0, 0.f); v1v = fmaxf(v1v, 0.f); }
        // log split-bf16 into At3 (tail GEMM operand), [Ah|Ah|Al]
        {
            __nv_bfloat162 hh;
            hh.x = __float2bfloat16(v0); hh.y = __float2bfloat16(v1v);
            __nv_bfloat162 ll;
            ll.x = __float2bfloat16(v0 - __bfloat162float(hh.x));
            ll.y = __float2bfloat16(v1v - __bfloat162float(hh.y));
            size_t base = (size_t)row1 * 3840;
            *(__nv_bfloat162*)&g_At3[base + h0] = hh;
            *(__nv_bfloat162*)&g_At3[base + 1280 + h0] = hh;
            *(__nv_bfloat162*)&g_At3[base + 2560 + h0] = ll;
            if (H0 < 128) {                       // v1 head -> memory'
                __stcg(&g_memT[nxt][h0 * 64 + b1], v0);
                __stcg(&g_memT[nxt][(h0 + 1) * 64 + b1], v1v);
                if (t + 1 < NT) {
                    size_t b2a = (size_t)(row1 + 1) * 3840;
                    *(__nv_bfloat162*)&g_At3[b2a + 1024 + h0] = hh;
                    *(__nv_bfloat162*)&g_At3[b2a + 2304 + h0] = hh;
                    *(__nv_bfloat162*)&g_At3[b2a + 3584 + h0] = ll;
                }
            }
        }
        v1s[(hp * 2) * 64 + b1] = v0;
        v1s[(hp * 2 + 1) * 64 + b1] = v1v;
        __syncthreads();

        // ===== stage 2: v2-head partial from own v1 chunk + own mem chunk =====
        {
            float acc[4][8];
#pragma unroll
            for (int i = 0; i < 4; i++)
#pragma unroll
                for (int j = 0; j < 8; j++) acc[i][j] = 0.f;
#pragma unroll
            for (int k = 0; k < 8; k++) {
                float4 w = *(float4*)&sW12[k * 128 + o0];
                float4 x0 = *(float4*)&v1s[k * 64 + b0];
                float4 x1 = *(float4*)&v1s[k * 64 + b0 + 4];
                float wv[4] = {w.x, w.y, w.z, w.w};
                float xv[8] = {x0.x, x0.y, x0.z, x0.w, x1.x, x1.y, x1.z, x1.w};
#pragma unroll
                for (int i = 0; i < 4; i++)
#pragma unroll
                    for (int j = 0; j < 8; j++) acc[i][j] += wv[i] * xv[j];
            }
#pragma unroll
            for (int ml = 0; ml < 2; ml++) {
                float4 w = *(float4*)&sW2m[ml * 128 + o0];
                float4 x0 = *(float4*)&sMem[(M0 + ml) * 64 + b0];
                float4 x1 = *(float4*)&sMem[(M0 + ml) * 64 + b0 + 4];
                float wv[4] = {w.x, w.y, w.z, w.w};
                float xv[8] = {x0.x, x0.y, x0.z, x0.w, x1.x, x1.y, x1.z, x1.w};
#pragma unroll
                for (int i = 0; i < 4; i++)
#pragma unroll
                    for (int j = 0; j < 8; j++) acc[i][j] += wv[i] * xv[j];
            }
#pragma unroll
            for (int i = 0; i < 4; i++) {
                size_t ob = (size_t)(blk * 128 + o0 + i) * 64 + b0;
                __stcg((float4*)&g_Bp[ob], make_float4(acc[i][0], acc[i][1], acc[i][2], acc[i][3]));
                __stcg((float4*)&g_Bp[ob + 4], make_float4(acc[i][4], acc[i][5], acc[i][6], acc[i][7]));
            }
        }
        gbar(tgt); tgt += NB;

        // ===== stage 3: reduce 128 partials for o-row = blk, sigmoid, writeback =====
        {
            float s = 0.f;
#pragma unroll 8
            for (int i = iq * 32; i < iq * 32 + 32; i++)
                s += __ldcg(&g_Bp[(size_t)(i * 128 + blk) * 64 + b3]);
            sRed[iq * 64 + b3] = s;
        }
        __syncthreads();
        if (tid < 64) {
            int b = tid;
            float s = sRed[b] + sRed[64 + b] + sRed[128 + b] + sRed[192 + b] + p2v;
            s = 1.f / (1.f + expf(-s));
            int row = b * NT + t;
            __stcg(&out[(size_t)row * 512 + blk], s);
            __stcg(&g_memT[nxt][(128 + blk) * 64 + b], s);
            if (t + 1 < NT) {
                __nv_bfloat16 h = __float2bfloat16(s);
                __nv_bfloat16 l = __float2bfloat16(s - __bfloat162float(h));
                size_t b2a = (size_t)(row + 1) * 3840;
                g_At3[b2a + 1152 + blk] = h;
                g_At3[b2a + 2432 + blk] = h;
                g_At3[b2a + 3712 + blk] = l;
            }
        }
        gbar(tgt); tgt += NB;
    }
}

// ---------------- launch ----------------
extern "C" void kernel_launch(void* const* d_in, const int* in_sizes, int n_in,
                              void* d_out, int out_size) {
    const float* X   = (const float*)d_in[0];
    const float* mem = (const float*)d_in[1];
    const float* W01 = (const float*)d_in[2];
    const float* b01 = (const float*)d_in[3];
    const float* W02 = (const float*)d_in[4];
    const float* b02 = (const float*)d_in[5];
    const float* W12 = (const float*)d_in[6];
    const float* b12 = (const float*)d_in[7];
    const float* Wm1 = (const float*)d_in[8];
    const float* bm1 = (const float*)d_in[9];
    const float* Wm2 = (const float*)d_in[10];
    const float* bm2 = (const float*)d_in[11];
    float* out = (float*)d_out;

    float *pre1, *pre2, *b1, *b2;
    __nv_bfloat16 *X3, *W013, *W023, *Wt3, *At3;
    cudaGetSymbolAddress((void**)&pre1, g_pre1);
    cudaGetSymbolAddress((void**)&pre2, g_pre2);
    cudaGetSymbolAddress((void**)&b1, g_bias1);
    cudaGetSymbolAddress((void**)&b2, g_bias2);
    cudaGetSymbolAddress((void**)&X3, g_X3);
    cudaGetSymbolAddress((void**)&W013, g_W013);
    cudaGetSymbolAddress((void**)&W023, g_W023);
    cudaGetSymbolAddress((void**)&Wt3, g_Wt3);
    cudaGetSymbolAddress((void**)&At3, g_At3);

    cudaFuncSetAttribute(loop_kernel, cudaFuncAttributeMaxDynamicSharedMemorySize,
                         SM_TOT * sizeof(float));

    prep_kernel<<<64, 256>>>(b01, bm1, b02, b12, bm2, mem);
    split3_kernel<<<2048, 256>>>(X, X3, 512, NROWS * 512, 1);
    split3_kernel<<<512, 256>>>(W01, W013, 512, 1024 * 512, 0);
    split3_kernel<<<256, 256>>>(W02, W023, 512, 512 * 512, 0);
    splitWtail_kernel<<<512, 256>>>(W12, Wm2);
    hgemm_kernel<<<dim3(8, 256), 256>>>(X3, W013, 1536, pre1, 1024, b1, nullptr, 0, 1);
    hgemm_kernel<<<dim3(4, 256), 256>>>(X3, W023, 1536, pre2, 512, b2, nullptr, 0, 1);
    loop_kernel<<<NB, 256, SM_TOT * sizeof(float)>>>(Wm1, W12, Wm2, out);
    hgemm_kernel<<<dim3(3, 256), 256>>>(At3, Wt3, 3840, out + 128, 512,
                                        nullptr, pre2 + 128, 512, 1);
}